// round 13
// baseline (speedup 1.0000x reference)
#include <cuda_runtime.h>

typedef unsigned long long ull;
#define NBATCH 4
#define NVERT 512
#define NROWS (NBATCH*NVERT)
#define ABS2 0x7fffffff7fffffffULL

__device__ __align__(256) float g_v [NROWS*64];
__device__ __align__(256) float g_v2[NROWS*64];
__device__ __align__(256) float g_wc[NROWS*64];
__device__ __align__(256) float g_wq[NROWS*64];
__device__ __align__(256) float g_m [NROWS*64];
__device__ __align__(256) float g_Aw[NROWS];
__device__ __align__(256) float g_Bw[NROWS];

static __device__ __forceinline__ ull f2add(ull a, ull b){ ull r; asm("add.rn.f32x2 %0,%1,%2;":"=l"(r):"l"(a),"l"(b)); return r; }
static __device__ __forceinline__ ull f2fma(ull a, ull b, ull c){ ull r; asm("fma.rn.f32x2 %0,%1,%2,%3;":"=l"(r):"l"(a),"l"(b),"l"(c)); return r; }
static __device__ __forceinline__ ull fsplat(float x){ ull r; asm("mov.b64 %0,{%1,%1};":"=l"(r):"f"(x)); return r; }
static __device__ __forceinline__ float2 funpack(ull v){ float2 f; asm("mov.b64 {%0,%1},%2;":"=f"(f.x),"=f"(f.y):"l"(v)); return f; }
static __device__ __forceinline__ float lrelu(float x){ return fmaxf(x,0.f) + 0.01f*fminf(x,0.f); }

static __device__ __forceinline__ unsigned sa(const void* p){
    unsigned a; asm("{ .reg .u64 t0; cvta.to.shared.u64 t0, %1; cvt.u32.u64 %0, t0; }":"=r"(a):"l"(p)); return a; }
#define CPA8(d,s)  asm volatile("cp.async.ca.shared.global [%0], [%1], 8;"::"r"(sa(d)),"l"(s))
#define CPA16(d,s) asm volatile("cp.async.cg.shared.global [%0], [%1], 16;"::"r"(sa(d)),"l"(s))
#define CPAC()  asm volatile("cp.async.commit_group;")
#define CPAW0() asm volatile("cp.async.wait_group 0;")
#define CPAW1() asm volatile("cp.async.wait_group 1;")

// ---------------------------------------------------------------------------
// K1: fused MLP (+embed on iter0). 16 rows/block, 128 blocks x 256 threads.
// (round-4 version — measured 3.3us)
// ---------------------------------------------------------------------------
#define MLPS (5*4224 + 3*1024 + 64)

__global__ void __launch_bounds__(256) k_mlp(
    const float* __restrict__ vert, const float* __restrict__ We, const float* __restrict__ be,
    const float* __restrict__ Wm, const float* __restrict__ bm,
    const float* __restrict__ Wq, const float* __restrict__ bq,
    const float* __restrict__ Wch,const float* __restrict__ bch,
    const float* __restrict__ wl)
{
    extern __shared__ float sm[];
    float* Wm_s = sm;
    float* Wq_s = sm + 4224;
    float* Wch_s= sm + 4*4224;
    float* vS   = sm + 5*4224;
    float* v2S  = vS + 1024;
    float* qS   = v2S + 1024;
    float* wl_s = qS + 1024;

    const int t = threadIdx.x;
    const int row0 = blockIdx.x*16;

    #pragma unroll
    for (int j=0;j<8;j++){ int p=t+j*256, k=p>>5, c=(p&31)*2; CPA8(&Wm_s[k*66+c], &Wm[k*64+c]); }
    if (t<32) CPA8(&wl_s[2*t], &wl[2*t]);
    if (!vert){
        #pragma unroll
        for (int j=0;j<2;j++){ int p=t+j*256, r=p>>5, c=(p&31)*2; CPA8(&vS[r*64+c], &g_v[(row0+r)*64+c]); }
    }
    CPAC();
    #pragma unroll
    for (int g=0; g<3; g++)
        #pragma unroll
        for (int j=0;j<8;j++){ int p=t+j*256, k=p>>5, c=(p&31)*2; CPA8(&Wq_s[g*4224+k*66+c], &Wq[k*192+g*64+c]); }
    #pragma unroll
    for (int j=0;j<8;j++){ int p=t+j*256, k=p>>5, c=(p&31)*2; CPA8(&Wch_s[k*66+c], &Wch[k*64+c]); }
    CPAC();

    if (vert){
        #pragma unroll
        for (int j=0;j<2;j++){
            int p=t+j*256, r=p>>5, c=(p&31)*2; int row=row0+r;
            float x=__ldg(&vert[row*3]), y=__ldg(&vert[row*3+1]), z=__ldg(&vert[row*3+2]);
            vS[r*64+c]   = __ldg(&be[c])   + x*__ldg(&We[c])   + y*__ldg(&We[64+c])   + z*__ldg(&We[128+c]);
            vS[r*64+c+1] = __ldg(&be[c+1]) + x*__ldg(&We[c+1]) + y*__ldg(&We[64+c+1]) + z*__ldg(&We[128+c+1]);
        }
    }
    CPAW1(); __syncthreads();

    const int r0 = (t>>5)*2, r1 = r0+1, c0 = (t&31)*2;
    const int rowA = row0 + r0, rowB = row0 + r1;

    {
        float a00=0,a01=0,a10=0,a11=0;
        #pragma unroll
        for (int k=0;k<64;k++){
            float2 w = *(const float2*)&Wm_s[k*66+c0];
            float vA = vS[r0*64+k], vB = vS[r1*64+k];
            a00 += vA*w.x; a01 += vA*w.y; a10 += vB*w.x; a11 += vB*w.y;
        }
        float b0=__ldg(&bm[c0]), b1=__ldg(&bm[c0+1]);
        float xA0=vS[r0*64+c0], xA1=vS[r0*64+c0+1], xB0=vS[r1*64+c0], xB1=vS[r1*64+c0+1];
        float v2A0 = xA0 + lrelu(a00+b0+xA0);
        float v2A1 = xA1 + lrelu(a01+b1+xA1);
        float v2B0 = xB0 + lrelu(a10+b0+xB0);
        float v2B1 = xB1 + lrelu(a11+b1+xB1);
        v2S[r0*64+c0]=v2A0; v2S[r0*64+c0+1]=v2A1;
        v2S[r1*64+c0]=v2B0; v2S[r1*64+c0+1]=v2B1;
        *(float2*)&g_v2[rowA*64+c0] = make_float2(v2A0,v2A1);
        *(float2*)&g_v2[rowB*64+c0] = make_float2(v2B0,v2B1);
    }
    CPAW0(); __syncthreads();

    {
        float aq0A=0,aq1A=0,aq0B=0,aq1B=0, ac0A=0,ac1A=0,ac0B=0,ac1B=0, am0A=0,am1A=0,am0B=0,am1B=0;
        #pragma unroll 8
        for (int k=0;k<64;k++){
            float vA = v2S[r0*64+k], vB = v2S[r1*64+k];
            float2 wq_ = *(const float2*)&Wq_s[       k*66+c0];
            float2 wc_ = *(const float2*)&Wq_s[4224 + k*66+c0];
            float2 wm_ = *(const float2*)&Wq_s[8448 + k*66+c0];
            aq0A+=vA*wq_.x; aq1A+=vA*wq_.y; aq0B+=vB*wq_.x; aq1B+=vB*wq_.y;
            ac0A+=vA*wc_.x; ac1A+=vA*wc_.y; ac0B+=vB*wc_.x; ac1B+=vB*wc_.y;
            am0A+=vA*wm_.x; am1A+=vA*wm_.y; am0B+=vB*wm_.x; am1B+=vB*wm_.y;
        }
        float bq0=__ldg(&bq[c0]), bq1=__ldg(&bq[c0+1]);
        qS[r0*64+c0]=aq0A+bq0; qS[r0*64+c0+1]=aq1A+bq1;
        qS[r1*64+c0]=aq0B+bq0; qS[r1*64+c0+1]=aq1B+bq1;

        float bc0=__ldg(&bq[64+c0]), bc1=__ldg(&bq[64+c0+1]);
        float wl0=wl_s[c0], wl1=wl_s[c0+1];
        float wcA0=wl0*(ac0A+bc0), wcA1=wl1*(ac1A+bc1);
        float wcB0=wl0*(ac0B+bc0), wcB1=wl1*(ac1B+bc1);
        *(float2*)&g_wc[rowA*64+c0] = make_float2(wcA0,wcA1);
        *(float2*)&g_wc[rowB*64+c0] = make_float2(wcB0,wcB1);
        float sA=wcA0+wcA1, sB=wcB0+wcB1;
        for (int off=16; off; off>>=1){ sA += __shfl_xor_sync(~0u,sA,off); sB += __shfl_xor_sync(~0u,sB,off); }
        if ((t&31)==0){ g_Aw[rowA]=sA; g_Aw[rowB]=sB; }

        float bmm0=__ldg(&bq[128+c0]), bmm1=__ldg(&bq[128+c0+1]);
        *(float2*)&g_m[rowA*64+c0] = make_float2(am0A+bmm0, am1A+bmm1);
        *(float2*)&g_m[rowB*64+c0] = make_float2(am0B+bmm0, am1B+bmm1);
    }
    __syncwarp();

    {
        float a00=0,a01=0,a10=0,a11=0;
        #pragma unroll
        for (int k=0;k<64;k++){
            float2 w = *(const float2*)&Wch_s[k*66+c0];
            float qA = qS[r0*64+k], qB = qS[r1*64+k];
            a00 += qA*w.x; a01 += qA*w.y; a10 += qB*w.x; a11 += qB*w.y;
        }
        float b0=__ldg(&bch[c0]), b1=__ldg(&bch[c0+1]);
        float wl0=wl_s[c0], wl1=wl_s[c0+1];
        float wqA0=wl0*(a00+b0), wqA1=wl1*(a01+b1);
        float wqB0=wl0*(a10+b0), wqB1=wl1*(a11+b1);
        *(float2*)&g_wq[rowA*64+c0] = make_float2(wqA0,wqA1);
        *(float2*)&g_wq[rowB*64+c0] = make_float2(wqB0,wqB1);
        float sA=wqA0+wqA1, sB=wqB0+wqB1;
        for (int off=16; off; off>>=1){ sA += __shfl_xor_sync(~0u,sA,off); sB += __shfl_xor_sync(~0u,sB,off); }
        if ((t&31)==0){ g_Bw[rowA]=sA; g_Bw[rowB]=sB; }
    }
}

// ---------------------------------------------------------------------------
// K2: attention. 16 q/block, grid (32,B) = 128 blocks, 512 threads, 1 block/SM.
// R12 structure; register-pressure cut: eb/vv loops unroll 1, no Bq precompute.
#define ATTNS 51664
#define NQ 16

__global__ void __launch_bounds__(512,1) k_attn(float* __restrict__ dout,
    const float* __restrict__ wl, const float* __restrict__ bl,
    const float* __restrict__ Wr, const float* __restrict__ br,
    const float* __restrict__ temp, const float* __restrict__ maskp)
{
    extern __shared__ float sm[];
    float* wcS   = sm;                   // 512x68 (wc, then m)
    float* L     = sm + 34816;           // 16x512
    float* Wr_s  = sm + 43008;           // 64x68
    float* wqs   = sm + 47360;           // 16x68
    float* v2s   = sm + 48448;           // 16x64
    float* s2s   = sm + 49472;           // 64
    float* Aws   = sm + 49536;           // 512
    float* Bws   = sm + 50048;           // 16
    float* lms   = sm + 50064;           // 512
    float* heads = sm + 50576;           // 16x68
    ull*   hpart = (ull*)sm;             // alias of wcS (after pass C reads done)

    const int t = threadIdx.x;
    const int b = blockIdx.y;
    const int rbase = b*NVERT + blockIdx.x*NQ;
    const float* wcBase = &g_wc[b*NVERT*64];
    const float* mBase  = &g_m [b*NVERT*64];

    // ---- prologue staging (CPA16 = 4 floats), one commit group ----
    if (t < 256){
        int r = t>>4, c = (t&15)*4;
        CPA16(&wqs[r*68+c], &g_wq[(rbase+r)*64+c]);
    } else {
        int u = t-256, r = u>>4, c = (u&15)*4;
        CPA16(&v2s[r*64+c], &g_v2[(rbase+r)*64+c]);
    }
    if (t < 128)      CPA16(&Aws[t*4], &g_Aw[b*NVERT + t*4]);
    else if (t < 256){ int u=t-128; CPA16(&lms[u*4], &maskp[b*NVERT + u*4]); }
    if (t < 4) CPA16(&Bws[t*4], &g_Bw[rbase + t*4]);
    #pragma unroll
    for (int j=0;j<2;j++){ int p=t+j*512, r=p>>4, c=(p&15)*4;
        CPA16(&Wr_s[r*68+c], &Wr[r*64+c]); }
    #pragma unroll
    for (int j=0;j<16;j++){ int p=t+j*512, r=p>>4, c=(p&15)*4;
        CPA16(&wcS[r*68+c], &wcBase[r*64+c]); }
    CPAC();
    if (t<64) s2s[t] = copysignf(0.495f, __ldg(&wl[t]));
    const float bl0  = __ldg(&bl[0]);
    const float invt = 1.0f/__ldg(&temp[0]);
    CPAW0(); __syncthreads();

    // ---- pass A: logits, all 512 v resident; tile 8q x 2v x 4e; unroll 1 ----
    const int qgA = t>>8;           // 0..1
    const int q0  = qgA*8;
    const int vl  = t&255;          // v rows: vl, vl+256

    ull acc[8][2];
    #pragma unroll
    for (int i=0;i<8;i++){ acc[i][0]=0; acc[i][1]=0; }

    #pragma unroll 1
    for (int eb=0; eb<16; eb++){
        ulonglong2 cA = *(const ulonglong2*)&wcS[ vl     *68 + eb*4];
        ulonglong2 cB = *(const ulonglong2*)&wcS[(vl+256)*68 + eb*4];
        ulonglong2 s  = *(const ulonglong2*)&s2s[eb*4];
        #pragma unroll
        for (int i=0;i<8;i++){
            ulonglong2 w = *(const ulonglong2*)&wqs[(q0+i)*68 + eb*4];
            acc[i][0] = f2fma(s.x, f2add(cA.x,w.x)&ABS2, acc[i][0]);
            acc[i][0] = f2fma(s.y, f2add(cA.y,w.y)&ABS2, acc[i][0]);
            acc[i][1] = f2fma(s.x, f2add(cB.x,w.x)&ABS2, acc[i][1]);
            acc[i][1] = f2fma(s.y, f2add(cB.y,w.y)&ABS2, acc[i][1]);
        }
    }
    #pragma unroll
    for (int j=0;j<2;j++){
        int vg = vl + j*256;
        float base = 0.505f*Aws[vg] + bl0;
        float lm = lms[vg];
        float p = invt*lm, mneg = -99999.f*(1.f-lm);
        #pragma unroll
        for (int i=0;i<8;i++){
            float2 f = funpack(acc[i][j]);
            L[(q0+i)*512 + vg] = (base + 0.505f*Bws[q0+i] + f.x + f.y)*p + mneg;
        }
    }
    __syncthreads();   // pass A done; wcS reads complete

    // ---- stream ALL of m into wcS (hidden under softmax) ----
    #pragma unroll
    for (int j=0;j<16;j++){ int p=t+j*512, r=p>>4, c=(p&15)*4;
        CPA16(&wcS[r*68+c], &mBase[r*64+c]); }
    CPAC();

    // ---- pass B: softmax, warp w handles q-row w (16 warps, 16 rows) ----
    {
        const int lane = t&31, w = t>>5;
        float lv[16];
        #pragma unroll
        for (int j=0;j<16;j++) lv[j] = L[w*512 + lane + 32*j];
        float mx = lv[0];
        #pragma unroll
        for (int j=1;j<16;j++) mx = fmaxf(mx, lv[j]);
        for (int off=16; off; off>>=1) mx = fmaxf(mx, __shfl_xor_sync(~0u, mx, off));
        float ev[16], ssum=0.f;
        #pragma unroll
        for (int j=0;j<16;j++){ ev[j] = __expf(lv[j]-mx); ssum += ev[j]; }
        for (int off=16; off; off>>=1) ssum += __shfl_xor_sync(~0u, ssum, off);
        float inv = 1.0f/ssum;
        #pragma unroll
        for (int j=0;j<16;j++) L[w*512 + lane + 32*j] = ev[j]*inv*lms[lane+32*j];
    }
    CPAW0(); __syncthreads();

    // ---- pass C: heads = probs @ m; tile 4q x 64v x 4e; unroll 1 ----
    const int em = t&15;            // 4-e block
    const int sv = (t>>4)&7;        // 64-v range
    const int qg = t>>7;            // 4-q group
    const int qc0 = qg*4;
    const int vb = sv*64;
    ull accC[4][2] = {{0,0},{0,0},{0,0},{0,0}};

    #pragma unroll 1
    for (int vv=0; vv<64; vv+=4){
        int r = vb+vv;
        ulonglong2 m0 = *(const ulonglong2*)&wcS[(r+0)*68 + em*4];
        ulonglong2 m1 = *(const ulonglong2*)&wcS[(r+1)*68 + em*4];
        ulonglong2 m2 = *(const ulonglong2*)&wcS[(r+2)*68 + em*4];
        ulonglong2 m3 = *(const ulonglong2*)&wcS[(r+3)*68 + em*4];
        #pragma unroll
        for (int i=0;i<4;i++){
            float4 p = *(const float4*)&L[(qc0+i)*512 + r];
            ull s0=fsplat(p.x), s1=fsplat(p.y), s2=fsplat(p.z), s3=fsplat(p.w);
            accC[i][0]=f2fma(s0,m0.x,accC[i][0]); accC[i][1]=f2fma(s0,m0.y,accC[i][1]);
            accC[i][0]=f2fma(s1,m1.x,accC[i][0]); accC[i][1]=f2fma(s1,m1.y,accC[i][1]);
            accC[i][0]=f2fma(s2,m2.x,accC[i][0]); accC[i][1]=f2fma(s2,m2.y,accC[i][1]);
            accC[i][0]=f2fma(s3,m3.x,accC[i][0]); accC[i][1]=f2fma(s3,m3.y,accC[i][1]);
        }
    }
    __syncthreads();   // all wcS(m) reads done; hpart may overwrite

    #pragma unroll
    for (int i=0;i<4;i++){
        int idx = ((sv*4+qg)*16+em)*4+i;
        hpart[idx*2+0] = accC[i][0];
        hpart[idx*2+1] = accC[i][1];
    }
    __syncthreads();

    // combine partials over sv(8) -> heads (lrelu). 512 threads: q = t>>5 (16 q).
    {
        const int q = t>>5, uc = t&31;
        const int hem = uc>>1, hu = uc&1, hqg = q>>2, hi = q&3;
        ull s = 0;
        #pragma unroll
        for (int svi=0; svi<8; svi++)
            s = f2add(s, hpart[(((svi*4+hqg)*16+hem)*4+hi)*2+hu]);
        float2 hv = funpack(s);
        heads[q*68 + uc*2]   = lrelu(hv.x);
        heads[q*68 + uc*2+1] = lrelu(hv.y);
    }
    __syncthreads();

    // ---- final: out = lrelu(heads)@Wr + br + v2 ----
    {
        const int q = t>>5, c0 = (t&31)*2;
        ull oacc = 0;
        #pragma unroll 8
        for (int e=0; e<64; e++)
            oacc = f2fma(fsplat(heads[q*68+e]), *(const ull*)&Wr_s[e*68+c0], oacc);
        float2 o = funpack(oacc);
        int row = rbase + q;
        float r0v = o.x + __ldg(&br[c0])   + v2s[q*64+c0];
        float r1v = o.y + __ldg(&br[c0+1]) + v2s[q*64+c0+1];
        *(float2*)&g_v[row*64+c0] = make_float2(r0v, r1v);
        if (dout) *(float2*)&dout[row*64+c0] = make_float2(r0v, r1v);
    }
}

// ---------------------------------------------------------------------------
extern "C" void kernel_launch(void* const* d_in, const int* in_sizes, int n_in,
                              void* d_out, int out_size)
{
    const float* vertices = (const float*)d_in[0];
    const float* mask     = (const float*)d_in[1];
    const float* W_embed  = (const float*)d_in[2];
    const float* b_embed  = (const float*)d_in[3];
    const float* W_mlp    = (const float*)d_in[4];
    const float* b_mlp    = (const float*)d_in[5];
    const float* W_qcm    = (const float*)d_in[6];
    const float* b_qcm    = (const float*)d_in[7];
    const float* W_ch     = (const float*)d_in[8];
    const float* b_ch     = (const float*)d_in[9];
    const float* W_logit  = (const float*)d_in[10];
    const float* b_logit  = (const float*)d_in[11];
    const float* W_red    = (const float*)d_in[12];
    const float* b_red    = (const float*)d_in[13];
    const float* temp     = (const float*)d_in[14];
    float* out = (float*)d_out;

    const int mlp_smem  = MLPS*4;
    const int attn_smem = ATTNS*4;
    cudaFuncSetAttribute(k_mlp,  cudaFuncAttributeMaxDynamicSharedMemorySize, mlp_smem);
    cudaFuncSetAttribute(k_attn, cudaFuncAttributeMaxDynamicSharedMemorySize, attn_smem);

    for (int i=0; i<3; i++){
        k_mlp<<<128,256,mlp_smem>>>(i==0 ? vertices : (const float*)nullptr, W_embed, b_embed,
                                    W_mlp + i*4096, b_mlp + i*64,
                                    W_qcm + i*12288, b_qcm + i*192,
                                    W_ch  + i*4096, b_ch  + i*64,
                                    W_logit + i*64);
        k_attn<<<dim3(32,NBATCH),512,attn_smem>>>(i==2 ? out : (float*)nullptr,
                                                  W_logit + i*64, b_logit + i,
                                                  W_red + i*4096, b_red + i*64,
                                                  temp + i, mask);
    }
}

// round 14
// speedup vs baseline: 1.0488x; 1.0488x over previous
#include <cuda_runtime.h>

typedef unsigned long long ull;
#define NBATCH 4
#define NVERT 512
#define NROWS (NBATCH*NVERT)
#define ABS2 0x7fffffff7fffffffULL

__device__ __align__(256) float g_v [NROWS*64];
__device__ __align__(256) float g_v2[NROWS*64];
__device__ __align__(256) float g_wc[NROWS*64];
__device__ __align__(256) float g_wq[NROWS*64];
__device__ __align__(256) float g_m [NROWS*64];
__device__ __align__(256) float g_Aw[NROWS];
__device__ __align__(256) float g_Bw[NROWS];

static __device__ __forceinline__ ull f2add(ull a, ull b){ ull r; asm("add.rn.f32x2 %0,%1,%2;":"=l"(r):"l"(a),"l"(b)); return r; }
static __device__ __forceinline__ ull f2fma(ull a, ull b, ull c){ ull r; asm("fma.rn.f32x2 %0,%1,%2,%3;":"=l"(r):"l"(a),"l"(b),"l"(c)); return r; }
static __device__ __forceinline__ ull fsplat(float x){ ull r; asm("mov.b64 %0,{%1,%1};":"=l"(r):"f"(x)); return r; }
static __device__ __forceinline__ float2 funpack(ull v){ float2 f; asm("mov.b64 {%0,%1},%2;":"=f"(f.x),"=f"(f.y):"l"(v)); return f; }
static __device__ __forceinline__ float lrelu(float x){ return fmaxf(x,0.f) + 0.01f*fminf(x,0.f); }

static __device__ __forceinline__ unsigned sa(const void* p){
    unsigned a; asm("{ .reg .u64 t0; cvta.to.shared.u64 t0, %1; cvt.u32.u64 %0, t0; }":"=r"(a):"l"(p)); return a; }
#define CPA8(d,s)  asm volatile("cp.async.ca.shared.global [%0], [%1], 8;"::"r"(sa(d)),"l"(s))
#define CPA16(d,s) asm volatile("cp.async.cg.shared.global [%0], [%1], 16;"::"r"(sa(d)),"l"(s))
#define CPAC()  asm volatile("cp.async.commit_group;")
#define CPAW0() asm volatile("cp.async.wait_group 0;")
#define CPAW1() asm volatile("cp.async.wait_group 1;")

// ---------------------------------------------------------------------------
// K1: fused MLP (+embed on iter0). 16 rows/block, 128 blocks x 256 threads.
// (round-4 version — measured 3.3us)
// ---------------------------------------------------------------------------
#define MLPS (5*4224 + 3*1024 + 64)

__global__ void __launch_bounds__(256) k_mlp(
    const float* __restrict__ vert, const float* __restrict__ We, const float* __restrict__ be,
    const float* __restrict__ Wm, const float* __restrict__ bm,
    const float* __restrict__ Wq, const float* __restrict__ bq,
    const float* __restrict__ Wch,const float* __restrict__ bch,
    const float* __restrict__ wl)
{
    extern __shared__ float sm[];
    float* Wm_s = sm;
    float* Wq_s = sm + 4224;
    float* Wch_s= sm + 4*4224;
    float* vS   = sm + 5*4224;
    float* v2S  = vS + 1024;
    float* qS   = v2S + 1024;
    float* wl_s = qS + 1024;

    const int t = threadIdx.x;
    const int row0 = blockIdx.x*16;

    #pragma unroll
    for (int j=0;j<8;j++){ int p=t+j*256, k=p>>5, c=(p&31)*2; CPA8(&Wm_s[k*66+c], &Wm[k*64+c]); }
    if (t<32) CPA8(&wl_s[2*t], &wl[2*t]);
    if (!vert){
        #pragma unroll
        for (int j=0;j<2;j++){ int p=t+j*256, r=p>>5, c=(p&31)*2; CPA8(&vS[r*64+c], &g_v[(row0+r)*64+c]); }
    }
    CPAC();
    #pragma unroll
    for (int g=0; g<3; g++)
        #pragma unroll
        for (int j=0;j<8;j++){ int p=t+j*256, k=p>>5, c=(p&31)*2; CPA8(&Wq_s[g*4224+k*66+c], &Wq[k*192+g*64+c]); }
    #pragma unroll
    for (int j=0;j<8;j++){ int p=t+j*256, k=p>>5, c=(p&31)*2; CPA8(&Wch_s[k*66+c], &Wch[k*64+c]); }
    CPAC();

    if (vert){
        #pragma unroll
        for (int j=0;j<2;j++){
            int p=t+j*256, r=p>>5, c=(p&31)*2; int row=row0+r;
            float x=__ldg(&vert[row*3]), y=__ldg(&vert[row*3+1]), z=__ldg(&vert[row*3+2]);
            vS[r*64+c]   = __ldg(&be[c])   + x*__ldg(&We[c])   + y*__ldg(&We[64+c])   + z*__ldg(&We[128+c]);
            vS[r*64+c+1] = __ldg(&be[c+1]) + x*__ldg(&We[c+1]) + y*__ldg(&We[64+c+1]) + z*__ldg(&We[128+c+1]);
        }
    }
    CPAW1(); __syncthreads();

    const int r0 = (t>>5)*2, r1 = r0+1, c0 = (t&31)*2;
    const int rowA = row0 + r0, rowB = row0 + r1;

    {
        float a00=0,a01=0,a10=0,a11=0;
        #pragma unroll
        for (int k=0;k<64;k++){
            float2 w = *(const float2*)&Wm_s[k*66+c0];
            float vA = vS[r0*64+k], vB = vS[r1*64+k];
            a00 += vA*w.x; a01 += vA*w.y; a10 += vB*w.x; a11 += vB*w.y;
        }
        float b0=__ldg(&bm[c0]), b1=__ldg(&bm[c0+1]);
        float xA0=vS[r0*64+c0], xA1=vS[r0*64+c0+1], xB0=vS[r1*64+c0], xB1=vS[r1*64+c0+1];
        float v2A0 = xA0 + lrelu(a00+b0+xA0);
        float v2A1 = xA1 + lrelu(a01+b1+xA1);
        float v2B0 = xB0 + lrelu(a10+b0+xB0);
        float v2B1 = xB1 + lrelu(a11+b1+xB1);
        v2S[r0*64+c0]=v2A0; v2S[r0*64+c0+1]=v2A1;
        v2S[r1*64+c0]=v2B0; v2S[r1*64+c0+1]=v2B1;
        *(float2*)&g_v2[rowA*64+c0] = make_float2(v2A0,v2A1);
        *(float2*)&g_v2[rowB*64+c0] = make_float2(v2B0,v2B1);
    }
    CPAW0(); __syncthreads();

    {
        float aq0A=0,aq1A=0,aq0B=0,aq1B=0, ac0A=0,ac1A=0,ac0B=0,ac1B=0, am0A=0,am1A=0,am0B=0,am1B=0;
        #pragma unroll 8
        for (int k=0;k<64;k++){
            float vA = v2S[r0*64+k], vB = v2S[r1*64+k];
            float2 wq_ = *(const float2*)&Wq_s[       k*66+c0];
            float2 wc_ = *(const float2*)&Wq_s[4224 + k*66+c0];
            float2 wm_ = *(const float2*)&Wq_s[8448 + k*66+c0];
            aq0A+=vA*wq_.x; aq1A+=vA*wq_.y; aq0B+=vB*wq_.x; aq1B+=vB*wq_.y;
            ac0A+=vA*wc_.x; ac1A+=vA*wc_.y; ac0B+=vB*wc_.x; ac1B+=vB*wc_.y;
            am0A+=vA*wm_.x; am1A+=vA*wm_.y; am0B+=vB*wm_.x; am1B+=vB*wm_.y;
        }
        float bq0=__ldg(&bq[c0]), bq1=__ldg(&bq[c0+1]);
        qS[r0*64+c0]=aq0A+bq0; qS[r0*64+c0+1]=aq1A+bq1;
        qS[r1*64+c0]=aq0B+bq0; qS[r1*64+c0+1]=aq1B+bq1;

        float bc0=__ldg(&bq[64+c0]), bc1=__ldg(&bq[64+c0+1]);
        float wl0=wl_s[c0], wl1=wl_s[c0+1];
        float wcA0=wl0*(ac0A+bc0), wcA1=wl1*(ac1A+bc1);
        float wcB0=wl0*(ac0B+bc0), wcB1=wl1*(ac1B+bc1);
        *(float2*)&g_wc[rowA*64+c0] = make_float2(wcA0,wcA1);
        *(float2*)&g_wc[rowB*64+c0] = make_float2(wcB0,wcB1);
        float sA=wcA0+wcA1, sB=wcB0+wcB1;
        for (int off=16; off; off>>=1){ sA += __shfl_xor_sync(~0u,sA,off); sB += __shfl_xor_sync(~0u,sB,off); }
        if ((t&31)==0){ g_Aw[rowA]=sA; g_Aw[rowB]=sB; }

        float bmm0=__ldg(&bq[128+c0]), bmm1=__ldg(&bq[128+c0+1]);
        *(float2*)&g_m[rowA*64+c0] = make_float2(am0A+bmm0, am1A+bmm1);
        *(float2*)&g_m[rowB*64+c0] = make_float2(am0B+bmm0, am1B+bmm1);
    }
    __syncwarp();

    {
        float a00=0,a01=0,a10=0,a11=0;
        #pragma unroll
        for (int k=0;k<64;k++){
            float2 w = *(const float2*)&Wch_s[k*66+c0];
            float qA = qS[r0*64+k], qB = qS[r1*64+k];
            a00 += qA*w.x; a01 += qA*w.y; a10 += qB*w.x; a11 += qB*w.y;
        }
        float b0=__ldg(&bch[c0]), b1=__ldg(&bch[c0+1]);
        float wl0=wl_s[c0], wl1=wl_s[c0+1];
        float wqA0=wl0*(a00+b0), wqA1=wl1*(a01+b1);
        float wqB0=wl0*(a10+b0), wqB1=wl1*(a11+b1);
        *(float2*)&g_wq[rowA*64+c0] = make_float2(wqA0,wqA1);
        *(float2*)&g_wq[rowB*64+c0] = make_float2(wqB0,wqB1);
        float sA=wqA0+wqA1, sB=wqB0+wqB1;
        for (int off=16; off; off>>=1){ sA += __shfl_xor_sync(~0u,sA,off); sB += __shfl_xor_sync(~0u,sB,off); }
        if ((t&31)==0){ g_Bw[rowA]=sA; g_Bw[rowB]=sB; }
    }
}

// ---------------------------------------------------------------------------
// K2: attention. 16 q/block, grid (32,B) = 128 blocks, 512 threads, 1 block/SM.
// R12 structure (best measured); eb unroll 4 -> 8 for a wider scheduling window.
#define ATTNS 51664
#define NQ 16

__global__ void __launch_bounds__(512,1) k_attn(float* __restrict__ dout,
    const float* __restrict__ wl, const float* __restrict__ bl,
    const float* __restrict__ Wr, const float* __restrict__ br,
    const float* __restrict__ temp, const float* __restrict__ maskp)
{
    extern __shared__ float sm[];
    float* wcS   = sm;                   // 512x68 (wc, then m)
    float* L     = sm + 34816;           // 16x512
    float* Wr_s  = sm + 43008;           // 64x68
    float* wqs   = sm + 47360;           // 16x68
    float* v2s   = sm + 48448;           // 16x64
    float* s2s   = sm + 49472;           // 64
    float* Aws   = sm + 49536;           // 512
    float* Bws   = sm + 50048;           // 16
    float* lms   = sm + 50064;           // 512
    float* heads = sm + 50576;           // 16x68
    ull*   hpart = (ull*)sm;             // alias of wcS (after pass C reads done)

    const int t = threadIdx.x;
    const int b = blockIdx.y;
    const int rbase = b*NVERT + blockIdx.x*NQ;
    const float* wcBase = &g_wc[b*NVERT*64];
    const float* mBase  = &g_m [b*NVERT*64];

    // ---- prologue staging (CPA16 = 4 floats), one commit group ----
    if (t < 256){
        int r = t>>4, c = (t&15)*4;
        CPA16(&wqs[r*68+c], &g_wq[(rbase+r)*64+c]);
    } else {
        int u = t-256, r = u>>4, c = (u&15)*4;
        CPA16(&v2s[r*64+c], &g_v2[(rbase+r)*64+c]);
    }
    if (t < 128)      CPA16(&Aws[t*4], &g_Aw[b*NVERT + t*4]);
    else if (t < 256){ int u=t-128; CPA16(&lms[u*4], &maskp[b*NVERT + u*4]); }
    if (t < 4) CPA16(&Bws[t*4], &g_Bw[rbase + t*4]);
    #pragma unroll
    for (int j=0;j<2;j++){ int p=t+j*512, r=p>>4, c=(p&15)*4;
        CPA16(&Wr_s[r*68+c], &Wr[r*64+c]); }
    #pragma unroll
    for (int j=0;j<16;j++){ int p=t+j*512, r=p>>4, c=(p&15)*4;
        CPA16(&wcS[r*68+c], &wcBase[r*64+c]); }
    CPAC();
    if (t<64) s2s[t] = copysignf(0.495f, __ldg(&wl[t]));
    const float bl0  = __ldg(&bl[0]);
    const float invt = 1.0f/__ldg(&temp[0]);
    CPAW0(); __syncthreads();

    // ---- pass A: logits, all 512 v resident; tile 8q x 2v x 4e; unroll 8 ----
    const int qgA = t>>8;           // 0..1
    const int q0  = qgA*8;
    const int vl  = t&255;          // v rows: vl, vl+256
    float Bq[8];
    #pragma unroll
    for (int i=0;i<8;i++) Bq[i] = 0.505f*Bws[q0+i];

    ull acc[8][2];
    #pragma unroll
    for (int i=0;i<8;i++){ acc[i][0]=0; acc[i][1]=0; }

    #pragma unroll 8
    for (int eb=0; eb<16; eb++){
        ulonglong2 cA = *(const ulonglong2*)&wcS[ vl     *68 + eb*4];
        ulonglong2 cB = *(const ulonglong2*)&wcS[(vl+256)*68 + eb*4];
        ulonglong2 s  = *(const ulonglong2*)&s2s[eb*4];
        #pragma unroll
        for (int i=0;i<8;i++){
            ulonglong2 w = *(const ulonglong2*)&wqs[(q0+i)*68 + eb*4];
            acc[i][0] = f2fma(s.x, f2add(cA.x,w.x)&ABS2, acc[i][0]);
            acc[i][0] = f2fma(s.y, f2add(cA.y,w.y)&ABS2, acc[i][0]);
            acc[i][1] = f2fma(s.x, f2add(cB.x,w.x)&ABS2, acc[i][1]);
            acc[i][1] = f2fma(s.y, f2add(cB.y,w.y)&ABS2, acc[i][1]);
        }
    }
    #pragma unroll
    for (int j=0;j<2;j++){
        int vg = vl + j*256;
        float base = 0.505f*Aws[vg] + bl0;
        float lm = lms[vg];
        float p = invt*lm, mneg = -99999.f*(1.f-lm);
        #pragma unroll
        for (int i=0;i<8;i++){
            float2 f = funpack(acc[i][j]);
            L[(q0+i)*512 + vg] = (base + Bq[i] + f.x + f.y)*p + mneg;
        }
    }
    __syncthreads();   // pass A done; wcS reads complete

    // ---- stream ALL of m into wcS (hidden under softmax) ----
    #pragma unroll
    for (int j=0;j<16;j++){ int p=t+j*512, r=p>>4, c=(p&15)*4;
        CPA16(&wcS[r*68+c], &mBase[r*64+c]); }
    CPAC();

    // ---- pass B: softmax, warp w handles q-row w (16 warps, 16 rows) ----
    {
        const int lane = t&31, w = t>>5;
        float lv[16];
        #pragma unroll
        for (int j=0;j<16;j++) lv[j] = L[w*512 + lane + 32*j];
        float mx = lv[0];
        #pragma unroll
        for (int j=1;j<16;j++) mx = fmaxf(mx, lv[j]);
        for (int off=16; off; off>>=1) mx = fmaxf(mx, __shfl_xor_sync(~0u, mx, off));
        float ev[16], ssum=0.f;
        #pragma unroll
        for (int j=0;j<16;j++){ ev[j] = __expf(lv[j]-mx); ssum += ev[j]; }
        for (int off=16; off; off>>=1) ssum += __shfl_xor_sync(~0u, ssum, off);
        float inv = 1.0f/ssum;
        #pragma unroll
        for (int j=0;j<16;j++) L[w*512 + lane + 32*j] = ev[j]*inv*lms[lane+32*j];
    }
    CPAW0(); __syncthreads();

    // ---- pass C: heads = probs @ m; all 512 v resident; tile 4q x 64v x 4e ----
    const int em = t&15;            // 4-e block
    const int sv = (t>>4)&7;        // 64-v range
    const int qg = t>>7;            // 4-q group
    const int qc0 = qg*4;
    const int vb = sv*64;
    ull accC[4][2] = {{0,0},{0,0},{0,0},{0,0}};

    #pragma unroll 2
    for (int vv=0; vv<64; vv+=4){
        int r = vb+vv;
        ulonglong2 m0 = *(const ulonglong2*)&wcS[(r+0)*68 + em*4];
        ulonglong2 m1 = *(const ulonglong2*)&wcS[(r+1)*68 + em*4];
        ulonglong2 m2 = *(const ulonglong2*)&wcS[(r+2)*68 + em*4];
        ulonglong2 m3 = *(const ulonglong2*)&wcS[(r+3)*68 + em*4];
        #pragma unroll
        for (int i=0;i<4;i++){
            float4 p = *(const float4*)&L[(qc0+i)*512 + r];
            ull s0=fsplat(p.x), s1=fsplat(p.y), s2=fsplat(p.z), s3=fsplat(p.w);
            accC[i][0]=f2fma(s0,m0.x,accC[i][0]); accC[i][1]=f2fma(s0,m0.y,accC[i][1]);
            accC[i][0]=f2fma(s1,m1.x,accC[i][0]); accC[i][1]=f2fma(s1,m1.y,accC[i][1]);
            accC[i][0]=f2fma(s2,m2.x,accC[i][0]); accC[i][1]=f2fma(s2,m2.y,accC[i][1]);
            accC[i][0]=f2fma(s3,m3.x,accC[i][0]); accC[i][1]=f2fma(s3,m3.y,accC[i][1]);
        }
    }
    __syncthreads();   // all wcS(m) reads done; hpart may overwrite

    #pragma unroll
    for (int i=0;i<4;i++){
        int idx = ((sv*4+qg)*16+em)*4+i;
        hpart[idx*2+0] = accC[i][0];
        hpart[idx*2+1] = accC[i][1];
    }
    __syncthreads();

    // combine partials over sv(8) -> heads (lrelu). 512 threads: q = t>>5 (16 q).
    {
        const int q = t>>5, uc = t&31;
        const int hem = uc>>1, hu = uc&1, hqg = q>>2, hi = q&3;
        ull s = 0;
        #pragma unroll
        for (int svi=0; svi<8; svi++)
            s = f2add(s, hpart[(((svi*4+hqg)*16+hem)*4+hi)*2+hu]);
        float2 hv = funpack(s);
        heads[q*68 + uc*2]   = lrelu(hv.x);
        heads[q*68 + uc*2+1] = lrelu(hv.y);
    }
    __syncthreads();

    // ---- final: out = lrelu(heads)@Wr + br + v2 ----
    {
        const int q = t>>5, c0 = (t&31)*2;
        ull oacc = 0;
        #pragma unroll 8
        for (int e=0; e<64; e++)
            oacc = f2fma(fsplat(heads[q*68+e]), *(const ull*)&Wr_s[e*68+c0], oacc);
        float2 o = funpack(oacc);
        int row = rbase + q;
        float r0v = o.x + __ldg(&br[c0])   + v2s[q*64+c0];
        float r1v = o.y + __ldg(&br[c0+1]) + v2s[q*64+c0+1];
        *(float2*)&g_v[row*64+c0] = make_float2(r0v, r1v);
        if (dout) *(float2*)&dout[row*64+c0] = make_float2(r0v, r1v);
    }
}

// ---------------------------------------------------------------------------
extern "C" void kernel_launch(void* const* d_in, const int* in_sizes, int n_in,
                              void* d_out, int out_size)
{
    const float* vertices = (const float*)d_in[0];
    const float* mask     = (const float*)d_in[1];
    const float* W_embed  = (const float*)d_in[2];
    const float* b_embed  = (const float*)d_in[3];
    const float* W_mlp    = (const float*)d_in[4];
    const float* b_mlp    = (const float*)d_in[5];
    const float* W_qcm    = (const float*)d_in[6];
    const float* b_qcm    = (const float*)d_in[7];
    const float* W_ch     = (const float*)d_in[8];
    const float* b_ch     = (const float*)d_in[9];
    const float* W_logit  = (const float*)d_in[10];
    const float* b_logit  = (const float*)d_in[11];
    const float* W_red    = (const float*)d_in[12];
    const float* b_red    = (const float*)d_in[13];
    const float* temp     = (const float*)d_in[14];
    float* out = (float*)d_out;

    const int mlp_smem  = MLPS*4;
    const int attn_smem = ATTNS*4;
    cudaFuncSetAttribute(k_mlp,  cudaFuncAttributeMaxDynamicSharedMemorySize, mlp_smem);
    cudaFuncSetAttribute(k_attn, cudaFuncAttributeMaxDynamicSharedMemorySize, attn_smem);

    for (int i=0; i<3; i++){
        k_mlp<<<128,256,mlp_smem>>>(i==0 ? vertices : (const float*)nullptr, W_embed, b_embed,
                                    W_mlp + i*4096, b_mlp + i*64,
                                    W_qcm + i*12288, b_qcm + i*192,
                                    W_ch  + i*4096, b_ch  + i*64,
                                    W_logit + i*64);
        k_attn<<<dim3(32,NBATCH),512,attn_smem>>>(i==2 ? out : (float*)nullptr,
                                                  W_logit + i*64, b_logit + i,
                                                  W_red + i*4096, b_red + i*64,
                                                  temp + i, mask);
    }
}